// round 3
// baseline (speedup 1.0000x reference)
#include <cuda_runtime.h>
#include <cuda_bf16.h>

#define N_NODES    500000
#define NODE_SIZE  512
#define GLOBAL_SIZE 256
#define HIDDEN_SIZE 1024
#define N_GRAPHS   4096
#define INPUT_SIZE (NODE_SIZE + GLOBAL_SIZE)   // 768

// ---------------- scratch (device globals; no allocation) ----------------
__device__ float g_A[N_GRAPHS * INPUT_SIZE];   // [4096 x 768]
__device__ float g_H[N_GRAPHS * HIDDEN_SIZE];  // [4096 x 1024]

// ---------------- kernel 1: fused per-graph mean + concat ----------------
// One block per graph. batch is SORTED int32, so the graph's rows are a
// contiguous range found by two binary searches. No atomics anywhere.
// 128 threads; each owns 4 columns (one float4) of the 512-wide feature.
__global__ __launch_bounds__(128) void mean_concat_kernel(
    const float* __restrict__ x, const int* __restrict__ batch,
    const float* __restrict__ u)
{
    const int g = blockIdx.x;
    const int tid = threadIdx.x;

    // lower_bound(g)
    int lo = 0, hi = N_NODES;
    while (lo < hi) { int mid = (lo + hi) >> 1; if (__ldg(&batch[mid]) < g) lo = mid + 1; else hi = mid; }
    const int start = lo;
    // lower_bound(g+1)
    hi = N_NODES;
    while (lo < hi) { int mid = (lo + hi) >> 1; if (__ldg(&batch[mid]) < g + 1) lo = mid + 1; else hi = mid; }
    const int end = lo;

    float4 acc = make_float4(0.f, 0.f, 0.f, 0.f);
    const float* xp = x + (size_t)start * NODE_SIZE + tid * 4;
#pragma unroll 4
    for (int r = start; r < end; ++r) {
        float4 v = *(const float4*)xp;
        acc.x += v.x; acc.y += v.y; acc.z += v.z; acc.w += v.w;
        xp += NODE_SIZE;
    }
    const int cnt = end - start;
    const float inv = (cnt > 0) ? 1.0f / (float)cnt : 0.0f;
    acc.x *= inv; acc.y *= inv; acc.z *= inv; acc.w *= inv;

    *(float4*)&g_A[(size_t)g * INPUT_SIZE + GLOBAL_SIZE + tid * 4] = acc;

    // copy u into the first 256 columns (64 threads x float4)
    if (tid < GLOBAL_SIZE / 4) {
        *(float4*)&g_A[(size_t)g * INPUT_SIZE + tid * 4] =
            *(const float4*)&u[(size_t)g * GLOBAL_SIZE + tid * 4];
    }
}

// ---------------- SELU ----------------
__device__ __forceinline__ float selu_f(float v) {
    const float alpha = 1.6732632423543772f;
    const float scale = 1.0507009873554805f;
    return v > 0.0f ? scale * v : scale * alpha * (expf(v) - 1.0f);
}

// ---------------- tiled fp32 GEMM body: C = act(A*B + bias) ----------------
// A: [M,K] row-major, B: [K,N] row-major, C: [M,N]. Dims multiples of tiles.
template <int BM, int BN, int BK, int TM, int TN, bool SELU>
__device__ __forceinline__ void gemm_body(
    const float* __restrict__ A, const float* __restrict__ B,
    const float* __restrict__ bias, float* __restrict__ C,
    int M, int N, int K)
{
    __shared__ float As[BK][BM];
    __shared__ float Bs[BK][BN];

    const int tid = threadIdx.x;
    const int tx = tid % (BN / TN);
    const int ty = tid / (BN / TN);
    const int row0 = blockIdx.y * BM;
    const int col0 = blockIdx.x * BN;

    float acc[TM][TN];
#pragma unroll
    for (int i = 0; i < TM; ++i)
#pragma unroll
        for (int j = 0; j < TN; ++j) acc[i][j] = 0.0f;

    const int a4 = BM * BK / 4;
    const int b4 = BK * BN / 4;

    for (int k0 = 0; k0 < K; k0 += BK) {
#pragma unroll
        for (int idx = tid; idx < a4; idx += 256) {
            int r = idx / (BK / 4);
            int c = (idx % (BK / 4)) * 4;
            float4 v = *(const float4*)&A[(size_t)(row0 + r) * K + k0 + c];
            As[c + 0][r] = v.x; As[c + 1][r] = v.y;
            As[c + 2][r] = v.z; As[c + 3][r] = v.w;
        }
#pragma unroll
        for (int idx = tid; idx < b4; idx += 256) {
            int r = idx / (BN / 4);
            int c = (idx % (BN / 4)) * 4;
            float4 v = *(const float4*)&B[(size_t)(k0 + r) * N + col0 + c];
            *(float4*)&Bs[r][c] = v;
        }
        __syncthreads();

#pragma unroll
        for (int kk = 0; kk < BK; ++kk) {
            float a_frag[TM], b_frag[TN];
#pragma unroll
            for (int i = 0; i < TM; ++i) a_frag[i] = As[kk][ty * TM + i];
#pragma unroll
            for (int j = 0; j < TN; ++j) b_frag[j] = Bs[kk][tx * TN + j];
#pragma unroll
            for (int i = 0; i < TM; ++i)
#pragma unroll
                for (int j = 0; j < TN; ++j)
                    acc[i][j] += a_frag[i] * b_frag[j];
        }
        __syncthreads();
    }

#pragma unroll
    for (int i = 0; i < TM; ++i) {
        int r = row0 + ty * TM + i;
#pragma unroll
        for (int j = 0; j < TN; ++j) {
            int c = col0 + tx * TN + j;
            float v = acc[i][j] + __ldg(&bias[c]);
            if (SELU) v = selu_f(v);
            C[(size_t)r * N + c] = v;
        }
    }
}

__global__ __launch_bounds__(256) void gemm1_kernel(
    const float* __restrict__ W1, const float* __restrict__ b1)
{
    gemm_body<128, 128, 8, 8, 8, true>(g_A, W1, b1, g_H,
                                       N_GRAPHS, HIDDEN_SIZE, INPUT_SIZE);
}

__global__ __launch_bounds__(256) void gemm2_kernel(
    const float* __restrict__ W2, const float* __restrict__ b2,
    float* __restrict__ out)
{
    gemm_body<128, 64, 8, 8, 4, false>(g_H, W2, b2, out,
                                       N_GRAPHS, GLOBAL_SIZE, HIDDEN_SIZE);
}

// ---------------- launch ----------------
extern "C" void kernel_launch(void* const* d_in, const int* in_sizes, int n_in,
                              void* d_out, int out_size)
{
    // Identify inputs by unique element counts (robust to ordering).
    const float* x     = nullptr;   // 256,000,000
    const float* u     = nullptr;   //   1,048,576
    const int*   batch = nullptr;   //     500,000 (int32 on device)
    const float* W1    = nullptr;   //     786,432
    const float* b1    = nullptr;   //       1,024
    const float* W2    = nullptr;   //     262,144
    const float* b2    = nullptr;   //         256

    for (int i = 0; i < n_in; ++i) {
        switch (in_sizes[i]) {
            case 256000000: x     = (const float*)d_in[i]; break;
            case 1048576:   u     = (const float*)d_in[i]; break;
            case 500000:    batch = (const int*)d_in[i];   break;
            case 786432:    W1    = (const float*)d_in[i]; break;
            case 1024:      b1    = (const float*)d_in[i]; break;
            case 262144:    W2    = (const float*)d_in[i]; break;
            case 256:       b2    = (const float*)d_in[i]; break;
            default: break; // edge_index (2000), edge_attr (16000): unused
        }
    }
    float* out = (float*)d_out;
    if (!x || !u || !batch || !W1 || !b1 || !W2 || !b2) return;

    // 1. A = [u | segment_mean(x, batch)]     (no atomics, no zero-pass)
    mean_concat_kernel<<<N_GRAPHS, 128>>>(x, batch, u);

    // 2. H = selu(A @ W1 + b1)   [4096 x 1024]
    {
        dim3 grid(HIDDEN_SIZE / 128, N_GRAPHS / 128);
        gemm1_kernel<<<grid, 256>>>(W1, b1);
    }
    // 3. out = H @ W2 + b2       [4096 x 256]
    {
        dim3 grid(GLOBAL_SIZE / 64, N_GRAPHS / 128);
        gemm2_kernel<<<grid, 256>>>(W2, b2, out);
    }
}

// round 4
// speedup vs baseline: 1.1130x; 1.1130x over previous
#include <cuda_runtime.h>
#include <cuda_bf16.h>

#define N_NODES    500000
#define NODE_SIZE  512
#define GLOBAL_SIZE 256
#define HIDDEN_SIZE 1024
#define N_GRAPHS   4096
#define INPUT_SIZE (NODE_SIZE + GLOBAL_SIZE)   // 768

typedef unsigned long long ull;

// ---------------- scratch (device globals; no allocation) ----------------
__device__ float g_A[N_GRAPHS * INPUT_SIZE];   // [4096 x 768]
__device__ float g_H[N_GRAPHS * HIDDEN_SIZE];  // [4096 x 1024]

// ---------------- kernel 1: fused per-graph mean + concat ----------------
// One block per graph. batch is SORTED int32; binary search the row range.
__global__ __launch_bounds__(128) void mean_concat_kernel(
    const float* __restrict__ x, const int* __restrict__ batch,
    const float* __restrict__ u)
{
    const int g = blockIdx.x;
    const int tid = threadIdx.x;

    int lo = 0, hi = N_NODES;
    while (lo < hi) { int mid = (lo + hi) >> 1; if (__ldg(&batch[mid]) < g) lo = mid + 1; else hi = mid; }
    const int start = lo;
    hi = N_NODES;
    while (lo < hi) { int mid = (lo + hi) >> 1; if (__ldg(&batch[mid]) < g + 1) lo = mid + 1; else hi = mid; }
    const int end = lo;

    float4 acc = make_float4(0.f, 0.f, 0.f, 0.f);
    const float* xp = x + (size_t)start * NODE_SIZE + tid * 4;
#pragma unroll 4
    for (int r = start; r < end; ++r) {
        float4 v = *(const float4*)xp;
        acc.x += v.x; acc.y += v.y; acc.z += v.z; acc.w += v.w;
        xp += NODE_SIZE;
    }
    const int cnt = end - start;
    const float inv = (cnt > 0) ? 1.0f / (float)cnt : 0.0f;
    acc.x *= inv; acc.y *= inv; acc.z *= inv; acc.w *= inv;

    *(float4*)&g_A[(size_t)g * INPUT_SIZE + GLOBAL_SIZE + tid * 4] = acc;

    if (tid < GLOBAL_SIZE / 4) {
        *(float4*)&g_A[(size_t)g * INPUT_SIZE + tid * 4] =
            *(const float4*)&u[(size_t)g * GLOBAL_SIZE + tid * 4];
    }
}

// ---------------- packed f32x2 helpers ----------------
__device__ __forceinline__ void ffma2(ull& d, ull a, ull b) {
    asm("fma.rn.f32x2 %0, %1, %2, %0;" : "+l"(d) : "l"(a), "l"(b));
}
__device__ __forceinline__ ull splat2(float a) {
    ull r; asm("mov.b64 %0, {%1, %1};" : "=l"(r) : "f"(a)); return r;
}
__device__ __forceinline__ void unpack2(ull v, float& lo, float& hi) {
    asm("mov.b64 {%0, %1}, %2;" : "=f"(lo), "=f"(hi) : "l"(v));
}

__device__ __forceinline__ float selu_f(float v) {
    const float alpha = 1.6732632423543772f;
    const float scale = 1.0507009873554805f;
    return v > 0.0f ? scale * v : scale * alpha * (expf(v) - 1.0f);
}

// ---------------- f32x2 double-buffered GEMM: C = act(A*B + bias) --------
// A:[M,K] row-major, B:[K,N] row-major, C:[M,N]. All dims multiples of tiles.
// Thread fragments are split-strided: TM=8 -> rows {ty*4..+3, BM/2+ty*4..+3},
// TN -> cols similarly. Accumulators are packed f32x2 (2 cols per u64).
template <int BM, int BN, int BK, int TM, int TN, bool SELU>
__device__ __forceinline__ void gemm_body(
    const float* __restrict__ A, const float* __restrict__ B,
    const float* __restrict__ bias, float* __restrict__ C,
    int M, int N, int K)
{
    constexpr int MFRAG = TM / 4;                 // 1 or 2
    constexpr int NFRAG = TN / 4;                 // 1 or 2
    constexpr int THREADS = (BM / TM) * (BN / TN);   // 256
    constexpr int APT = (BM * BK) / (4 * THREADS);   // float4/thread for A tile
    constexpr int BPT = (BK * BN) / (4 * THREADS);   // float4/thread for B tile
    constexpr int FBM = BM / MFRAG;               // frag base stride (rows)
    constexpr int FBN = BN / NFRAG;               // frag base stride (cols)

    __shared__ __align__(16) float As[2][BK][BM];   // transposed: As[k][m]
    __shared__ __align__(16) float Bs[2][BK][BN];

    const int tid = threadIdx.x;
    const int tx = tid % (BN / TN);
    const int ty = tid / (BN / TN);
    const int row0 = blockIdx.y * BM;
    const int col0 = blockIdx.x * BN;

    ull acc[TM][TN / 2];
#pragma unroll
    for (int i = 0; i < TM; ++i)
#pragma unroll
        for (int j = 0; j < TN / 2; ++j) acc[i][j] = 0ull;

    float4 pa[APT], pb[BPT];
    const int nk = K / BK;

    // ---- global load of tile t into registers ----
    auto loadg = [&](int t) {
#pragma unroll
        for (int s = 0; s < APT; ++s) {
            int idx = tid + s * THREADS;
            int r = idx / (BK / 4);
            int c = (idx % (BK / 4)) * 4;
            pa[s] = *(const float4*)&A[(size_t)(row0 + r) * K + t * BK + c];
        }
#pragma unroll
        for (int s = 0; s < BPT; ++s) {
            int idx = tid + s * THREADS;
            int r = idx / (BN / 4);
            int c = (idx % (BN / 4)) * 4;
            pb[s] = *(const float4*)&B[(size_t)(t * BK + r) * N + col0 + c];
        }
    };
    // ---- store registers into smem buffer ----
    auto stores = [&](int buf) {
#pragma unroll
        for (int s = 0; s < APT; ++s) {
            int idx = tid + s * THREADS;
            int r = idx / (BK / 4);
            int c = (idx % (BK / 4)) * 4;
            As[buf][c + 0][r] = pa[s].x;
            As[buf][c + 1][r] = pa[s].y;
            As[buf][c + 2][r] = pa[s].z;
            As[buf][c + 3][r] = pa[s].w;
        }
#pragma unroll
        for (int s = 0; s < BPT; ++s) {
            int idx = tid + s * THREADS;
            int r = idx / (BN / 4);
            int c = (idx % (BN / 4)) * 4;
            *(float4*)&Bs[buf][r][c] = pb[s];
        }
    };
    // ---- inner product on smem buffer ----
    auto compute = [&](int buf) {
#pragma unroll
        for (int kk = 0; kk < BK; ++kk) {
            ull a2[TM];
#pragma unroll
            for (int f = 0; f < MFRAG; ++f) {
                float4 av = *(const float4*)&As[buf][kk][f * FBM + ty * 4];
                a2[f * 4 + 0] = splat2(av.x);
                a2[f * 4 + 1] = splat2(av.y);
                a2[f * 4 + 2] = splat2(av.z);
                a2[f * 4 + 3] = splat2(av.w);
            }
            ull b2[TN / 2];
#pragma unroll
            for (int f = 0; f < NFRAG; ++f) {
                ulonglong2 bv = *(const ulonglong2*)&Bs[buf][kk][f * FBN + tx * 4];
                b2[f * 2 + 0] = bv.x;
                b2[f * 2 + 1] = bv.y;
            }
#pragma unroll
            for (int i = 0; i < TM; ++i)
#pragma unroll
                for (int j = 0; j < TN / 2; ++j)
                    ffma2(acc[i][j], a2[i], b2[j]);
        }
    };

    // ---- pipelined mainloop ----
    loadg(0);
    stores(0);
    __syncthreads();
    for (int t = 0; t < nk; ++t) {
        if (t + 1 < nk) loadg(t + 1);
        compute(t & 1);
        if (t + 1 < nk) {
            stores((t + 1) & 1);
            __syncthreads();
        }
    }

    // ---- epilogue: unpack, bias, act, store ----
#pragma unroll
    for (int fi = 0; fi < MFRAG; ++fi) {
#pragma unroll
        for (int ii = 0; ii < 4; ++ii) {
            int i = fi * 4 + ii;
            int r = row0 + fi * FBM + ty * 4 + ii;
#pragma unroll
            for (int fj = 0; fj < NFRAG; ++fj) {
                int c = col0 + fj * FBN + tx * 4;
                float4 bv = *(const float4*)&bias[c];
                float v0, v1, v2, v3;
                unpack2(acc[i][fj * 2 + 0], v0, v1);
                unpack2(acc[i][fj * 2 + 1], v2, v3);
                v0 += bv.x; v1 += bv.y; v2 += bv.z; v3 += bv.w;
                if (SELU) { v0 = selu_f(v0); v1 = selu_f(v1); v2 = selu_f(v2); v3 = selu_f(v3); }
                float4 o; o.x = v0; o.y = v1; o.z = v2; o.w = v3;
                *(float4*)&C[(size_t)r * N + c] = o;
            }
        }
    }
}

__global__ __launch_bounds__(256) void gemm1_kernel(
    const float* __restrict__ W1, const float* __restrict__ b1)
{
    gemm_body<128, 128, 16, 8, 8, true>(g_A, W1, b1, g_H,
                                        N_GRAPHS, HIDDEN_SIZE, INPUT_SIZE);
}

__global__ __launch_bounds__(256) void gemm2_kernel(
    const float* __restrict__ W2, const float* __restrict__ b2,
    float* __restrict__ out)
{
    gemm_body<128, 64, 16, 8, 4, false>(g_H, W2, b2, out,
                                        N_GRAPHS, GLOBAL_SIZE, HIDDEN_SIZE);
}

// ---------------- launch ----------------
extern "C" void kernel_launch(void* const* d_in, const int* in_sizes, int n_in,
                              void* d_out, int out_size)
{
    const float* x     = nullptr;   // 256,000,000
    const float* u     = nullptr;   //   1,048,576
    const int*   batch = nullptr;   //     500,000 (int32 on device)
    const float* W1    = nullptr;   //     786,432
    const float* b1    = nullptr;   //       1,024
    const float* W2    = nullptr;   //     262,144
    const float* b2    = nullptr;   //         256

    for (int i = 0; i < n_in; ++i) {
        switch (in_sizes[i]) {
            case 256000000: x     = (const float*)d_in[i]; break;
            case 1048576:   u     = (const float*)d_in[i]; break;
            case 500000:    batch = (const int*)d_in[i];   break;
            case 786432:    W1    = (const float*)d_in[i]; break;
            case 1024:      b1    = (const float*)d_in[i]; break;
            case 262144:    W2    = (const float*)d_in[i]; break;
            case 256:       b2    = (const float*)d_in[i]; break;
            default: break; // edge_index (2000), edge_attr (16000): unused
        }
    }
    float* out = (float*)d_out;
    if (!x || !u || !batch || !W1 || !b1 || !W2 || !b2) return;

    // 1. A = [u | segment_mean(x, batch)]
    mean_concat_kernel<<<N_GRAPHS, 128>>>(x, batch, u);

    // 2. H = selu(A @ W1 + b1)   [4096 x 1024]
    {
        dim3 grid(HIDDEN_SIZE / 128, N_GRAPHS / 128);
        gemm1_kernel<<<grid, 256>>>(W1, b1);
    }
    // 3. out = H @ W2 + b2       [4096 x 256]
    {
        dim3 grid(GLOBAL_SIZE / 64, N_GRAPHS / 128);
        gemm2_kernel<<<grid, 256>>>(W2, b2, out);
    }
}

// round 8
// speedup vs baseline: 1.2516x; 1.1246x over previous
#include <cuda_runtime.h>
#include <cuda_bf16.h>
#include <mma.h>
#include <cstdint>

using namespace nvcuda;

#define N_NODES     500000
#define NODE_SIZE   512
#define GLOBAL_SIZE 256
#define HIDDEN_SIZE 1024
#define N_GRAPHS    4096
#define INPUT_SIZE  768

typedef __nv_bfloat16 bf16;

// ---------------- scratch (device globals; no allocation) ----------------
__device__ bf16  g_Ahi[N_GRAPHS * INPUT_SIZE];
__device__ bf16  g_Alo[N_GRAPHS * INPUT_SIZE];
__device__ bf16  g_W1Thi[HIDDEN_SIZE * INPUT_SIZE];   // [N=1024][K=768]
__device__ bf16  g_W1Tlo[HIDDEN_SIZE * INPUT_SIZE];
__device__ bf16  g_W2Thi[GLOBAL_SIZE * HIDDEN_SIZE];  // [N=256][K=1024]
__device__ bf16  g_W2Tlo[GLOBAL_SIZE * HIDDEN_SIZE];
__device__ bf16  g_Hhi[N_GRAPHS * HIDDEN_SIZE];
__device__ bf16  g_Hlo[N_GRAPHS * HIDDEN_SIZE];
__device__ float g_C1[N_GRAPHS * HIDDEN_SIZE];        // raw GEMM1 output

// ---------------- helpers ----------------
__device__ __forceinline__ void split_bf(float v, bf16& hi, bf16& lo) {
    hi = __float2bfloat16(v);
    lo = __float2bfloat16(v - __bfloat162float(hi));
}
__device__ __forceinline__ float selu_f(float v) {
    const float alpha = 1.6732632423543772f;
    const float scale = 1.0507009873554805f;
    return v > 0.0f ? scale * v : scale * alpha * (expf(v) - 1.0f);
}

// ---------------- kernel 1: fused per-graph mean + concat (-> bf16 splits) ----
__global__ __launch_bounds__(128) void mean_concat_kernel(
    const float* __restrict__ x, const int* __restrict__ batch,
    const float* __restrict__ u)
{
    const int g = blockIdx.x;
    const int tid = threadIdx.x;

    int lo = 0, hi = N_NODES;
    while (lo < hi) { int mid = (lo + hi) >> 1; if (__ldg(&batch[mid]) < g) lo = mid + 1; else hi = mid; }
    const int start = lo;
    hi = N_NODES;
    while (lo < hi) { int mid = (lo + hi) >> 1; if (__ldg(&batch[mid]) < g + 1) lo = mid + 1; else hi = mid; }
    const int end = lo;

    float4 acc = make_float4(0.f, 0.f, 0.f, 0.f);
    const float* xp = x + (size_t)start * NODE_SIZE + tid * 4;
#pragma unroll 4
    for (int r = start; r < end; ++r) {
        float4 v = *(const float4*)xp;
        acc.x += v.x; acc.y += v.y; acc.z += v.z; acc.w += v.w;
        xp += NODE_SIZE;
    }
    const int cnt = end - start;
    const float inv = (cnt > 0) ? 1.0f / (float)cnt : 0.0f;
    acc.x *= inv; acc.y *= inv; acc.z *= inv; acc.w *= inv;

    {
        size_t base = (size_t)g * INPUT_SIZE + GLOBAL_SIZE + tid * 4;
        bf16 h, l;
        split_bf(acc.x, h, l); g_Ahi[base]     = h; g_Alo[base]     = l;
        split_bf(acc.y, h, l); g_Ahi[base + 1] = h; g_Alo[base + 1] = l;
        split_bf(acc.z, h, l); g_Ahi[base + 2] = h; g_Alo[base + 2] = l;
        split_bf(acc.w, h, l); g_Ahi[base + 3] = h; g_Alo[base + 3] = l;
    }
    if (tid < GLOBAL_SIZE / 4) {
        float4 v = *(const float4*)&u[(size_t)g * GLOBAL_SIZE + tid * 4];
        size_t base = (size_t)g * INPUT_SIZE + tid * 4;
        bf16 h, l;
        split_bf(v.x, h, l); g_Ahi[base]     = h; g_Alo[base]     = l;
        split_bf(v.y, h, l); g_Ahi[base + 1] = h; g_Alo[base + 1] = l;
        split_bf(v.z, h, l); g_Ahi[base + 2] = h; g_Alo[base + 2] = l;
        split_bf(v.w, h, l); g_Ahi[base + 3] = h; g_Alo[base + 3] = l;
    }
}

// ---------------- prep: transpose + split weights ----------------
__global__ void prep_w1t_kernel(const float* __restrict__ W1) {
    int idx = blockIdx.x * blockDim.x + threadIdx.x;
    if (idx >= HIDDEN_SIZE * INPUT_SIZE) return;
    int n = idx / INPUT_SIZE, k = idx % INPUT_SIZE;
    float v = __ldg(&W1[(size_t)k * HIDDEN_SIZE + n]);
    bf16 hi, lo; split_bf(v, hi, lo);
    g_W1Thi[idx] = hi; g_W1Tlo[idx] = lo;
}
__global__ void prep_w2t_kernel(const float* __restrict__ W2) {
    int idx = blockIdx.x * blockDim.x + threadIdx.x;
    if (idx >= GLOBAL_SIZE * HIDDEN_SIZE) return;
    int n = idx / HIDDEN_SIZE, k = idx % HIDDEN_SIZE;
    float v = __ldg(&W2[(size_t)k * GLOBAL_SIZE + n]);
    bf16 hi, lo; split_bf(v, hi, lo);
    g_W2Thi[idx] = hi; g_W2Tlo[idx] = lo;
}

// ---------------- wmma bf16-split GEMM body: C_raw = A @ B^T (fp32) ----------
// A rows [M][K] hi/lo bf16; B rows [N][K] hi/lo bf16 (wmma matrix_b col_major
// with ldm = row stride gives B^T directly). 3 passes: AhBh + AhBl + AlBh.
// BN=128, BK=32, 256 threads = 8 warps (2 M x 4 N); warp tile (BM/2) x 32.
template <int BM>
__device__ __forceinline__ void wmma_gemm_body(
    const bf16* __restrict__ Ah, const bf16* __restrict__ Al,
    const bf16* __restrict__ Bh, const bf16* __restrict__ Bl,
    float* __restrict__ C, int K_TOTAL, int N_TOTAL)
{
    constexpr int BN = 128, BK = 32, PAD = 48;   // 96B rows: 32B-aligned for wmma
    constexpr int WM = BM / 2;                   // 64 or 32
    constexpr int MF = WM / 16;                  // 4 or 2
    constexpr int NF = 2;                        // warp N tile = 32

    extern __shared__ __align__(32) char sm_raw[];
    bf16* sAh = (bf16*)sm_raw;
    bf16* sAl = sAh + BM * PAD;
    bf16* sBh = sAl + BM * PAD;
    bf16* sBl = sBh + BN * PAD;

    const int tid = threadIdx.x;
    const int wid = tid >> 5;
    const int warp_m = wid >> 2;   // 0..1
    const int warp_n = wid & 3;    // 0..3
    const int m0 = blockIdx.y * BM;
    const int n0 = blockIdx.x * BN;

    wmma::fragment<wmma::accumulator, 16, 16, 16, float> acc[MF][NF];
#pragma unroll
    for (int mi = 0; mi < MF; ++mi)
#pragma unroll
        for (int ni = 0; ni < NF; ++ni) wmma::fill_fragment(acc[mi][ni], 0.0f);

    const int nk = K_TOTAL / BK;
    for (int t = 0; t < nk; ++t) {
        const int k0 = t * BK;
        for (int idx = tid; idx < BM * 4; idx += 256) {
            int r = idx >> 2, c8 = (idx & 3) * 8;
            *(uint4*)&sAh[r * PAD + c8] = *(const uint4*)&Ah[(size_t)(m0 + r) * K_TOTAL + k0 + c8];
            *(uint4*)&sAl[r * PAD + c8] = *(const uint4*)&Al[(size_t)(m0 + r) * K_TOTAL + k0 + c8];
        }
        for (int idx = tid; idx < BN * 4; idx += 256) {
            int r = idx >> 2, c8 = (idx & 3) * 8;
            *(uint4*)&sBh[r * PAD + c8] = *(const uint4*)&Bh[(size_t)(n0 + r) * K_TOTAL + k0 + c8];
            *(uint4*)&sBl[r * PAD + c8] = *(const uint4*)&Bl[(size_t)(n0 + r) * K_TOTAL + k0 + c8];
        }
        __syncthreads();

#pragma unroll
        for (int ks = 0; ks < BK / 16; ++ks) {
            wmma::fragment<wmma::matrix_b, 16, 16, 16, bf16, wmma::col_major> fbh[NF], fbl[NF];
#pragma unroll
            for (int ni = 0; ni < NF; ++ni) {
                wmma::load_matrix_sync(fbh[ni], &sBh[(warp_n * 32 + ni * 16) * PAD + ks * 16], PAD);
                wmma::load_matrix_sync(fbl[ni], &sBl[(warp_n * 32 + ni * 16) * PAD + ks * 16], PAD);
            }
#pragma unroll
            for (int mi = 0; mi < MF; ++mi) {
                wmma::fragment<wmma::matrix_a, 16, 16, 16, bf16, wmma::row_major> fah, fal;
                wmma::load_matrix_sync(fah, &sAh[(warp_m * WM + mi * 16) * PAD + ks * 16], PAD);
                wmma::load_matrix_sync(fal, &sAl[(warp_m * WM + mi * 16) * PAD + ks * 16], PAD);
#pragma unroll
                for (int ni = 0; ni < NF; ++ni) {
                    wmma::mma_sync(acc[mi][ni], fah, fbh[ni], acc[mi][ni]);
                    wmma::mma_sync(acc[mi][ni], fah, fbl[ni], acc[mi][ni]);
                    wmma::mma_sync(acc[mi][ni], fal, fbh[ni], acc[mi][ni]);
                }
            }
        }
        __syncthreads();
    }

#pragma unroll
    for (int mi = 0; mi < MF; ++mi)
#pragma unroll
        for (int ni = 0; ni < NF; ++ni) {
            float* cp = &C[(size_t)(m0 + warp_m * WM + mi * 16) * N_TOTAL
                           + n0 + warp_n * 32 + ni * 16];
            wmma::store_matrix_sync(cp, acc[mi][ni], N_TOTAL, wmma::mem_row_major);
        }
}

// Wrappers: device-global scratch referenced FROM DEVICE CODE (the R4 lesson —
// __device__ symbols must never be passed as kernel args from host code).
__global__ __launch_bounds__(256) void gemm1_kernel() {
    wmma_gemm_body<128>(g_Ahi, g_Alo, g_W1Thi, g_W1Tlo, g_C1,
                        INPUT_SIZE, HIDDEN_SIZE);
}
__global__ __launch_bounds__(256) void gemm2_kernel(float* __restrict__ out) {
    wmma_gemm_body<64>(g_Hhi, g_Hlo, g_W2Thi, g_W2Tlo, out,
                       HIDDEN_SIZE, GLOBAL_SIZE);
}

// ---------------- postproc 1: H = selu(C1 + b1) -> bf16 hi/lo ----------------
__global__ void post1_kernel(const float* __restrict__ b1) {
    int idx = blockIdx.x * blockDim.x + threadIdx.x;
    if (idx >= N_GRAPHS * HIDDEN_SIZE) return;
    float v = selu_f(g_C1[idx] + __ldg(&b1[idx & (HIDDEN_SIZE - 1)]));
    bf16 hi, lo; split_bf(v, hi, lo);
    g_Hhi[idx] = hi; g_Hlo[idx] = lo;
}

// ---------------- postproc 2: out += b2 (in place) ----------------
__global__ void post2_kernel(float* __restrict__ out, const float* __restrict__ b2) {
    int idx = blockIdx.x * blockDim.x + threadIdx.x;
    if (idx >= N_GRAPHS * GLOBAL_SIZE) return;
    out[idx] += __ldg(&b2[idx & (GLOBAL_SIZE - 1)]);
}

// ---------------- launch ----------------
extern "C" void kernel_launch(void* const* d_in, const int* in_sizes, int n_in,
                              void* d_out, int out_size)
{
    const float* x     = nullptr;   // 256,000,000
    const float* u     = nullptr;   //   1,048,576
    const int*   batch = nullptr;   //     500,000 (int32 on device)
    const float* W1    = nullptr;   //     786,432
    const float* b1    = nullptr;   //       1,024
    const float* W2    = nullptr;   //     262,144
    const float* b2    = nullptr;   //         256

    for (int i = 0; i < n_in; ++i) {
        switch (in_sizes[i]) {
            case 256000000: x     = (const float*)d_in[i]; break;
            case 1048576:   u     = (const float*)d_in[i]; break;
            case 500000:    batch = (const int*)d_in[i];   break;
            case 786432:    W1    = (const float*)d_in[i]; break;
            case 1024:      b1    = (const float*)d_in[i]; break;
            case 262144:    W2    = (const float*)d_in[i]; break;
            case 256:       b2    = (const float*)d_in[i]; break;
            default: break; // edge_index (2000), edge_attr (16000): unused
        }
    }
    float* out = (float*)d_out;
    if (!x || !u || !batch || !W1 || !b1 || !W2 || !b2) return;

    constexpr int PAD = 48;
    const int smem1 = (128 + 128 + 128 + 128) * PAD * 2;   // 49152
    const int smem2 = (64 + 64 + 128 + 128) * PAD * 2;     // 36864
    cudaFuncSetAttribute(gemm1_kernel,
                         cudaFuncAttributeMaxDynamicSharedMemorySize, smem1);
    cudaFuncSetAttribute(gemm2_kernel,
                         cudaFuncAttributeMaxDynamicSharedMemorySize, smem2);

    // 1. A = [u | segment_mean(x, batch)]  (bf16 hi/lo)
    mean_concat_kernel<<<N_GRAPHS, 128>>>(x, batch, u);

    // 2. weight transpose + split
    prep_w1t_kernel<<<(HIDDEN_SIZE * INPUT_SIZE + 255) / 256, 256>>>(W1);
    prep_w2t_kernel<<<(GLOBAL_SIZE * HIDDEN_SIZE + 255) / 256, 256>>>(W2);

    // 3. C1 = A @ W1 (raw fp32)   [4096 x 1024]
    {
        dim3 grid(HIDDEN_SIZE / 128, N_GRAPHS / 128);
        gemm1_kernel<<<grid, 256, smem1>>>();
    }
    // 4. H = selu(C1 + b1) -> bf16 hi/lo
    post1_kernel<<<(N_GRAPHS * HIDDEN_SIZE + 255) / 256, 256>>>(b1);

    // 5. out_raw = H @ W2 (fp32)  [4096 x 256]
    {
        dim3 grid(GLOBAL_SIZE / 128, N_GRAPHS / 64);
        gemm2_kernel<<<grid, 256, smem2>>>(out);
    }
    // 6. out += b2
    post2_kernel<<<(N_GRAPHS * GLOBAL_SIZE + 255) / 256, 256>>>(out, b2);
}

// round 9
// speedup vs baseline: 1.5878x; 1.2686x over previous
#include <cuda_runtime.h>
#include <cuda_bf16.h>
#include <mma.h>
#include <cstdint>

using namespace nvcuda;

#define N_NODES     500000
#define NODE_SIZE   512
#define GLOBAL_SIZE 256
#define HIDDEN_SIZE 1024
#define N_GRAPHS    4096
#define INPUT_SIZE  768

typedef __nv_bfloat16 bf16;

// ---------------- scratch (device globals; no allocation) ----------------
__device__ bf16 g_Ahi[N_GRAPHS * INPUT_SIZE];
__device__ bf16 g_Alo[N_GRAPHS * INPUT_SIZE];
__device__ bf16 g_W1Thi[HIDDEN_SIZE * INPUT_SIZE];   // [N=1024][K=768]
__device__ bf16 g_W1Tlo[HIDDEN_SIZE * INPUT_SIZE];
__device__ bf16 g_W2Thi[GLOBAL_SIZE * HIDDEN_SIZE];  // [N=256][K=1024]
__device__ bf16 g_W2Tlo[GLOBAL_SIZE * HIDDEN_SIZE];
__device__ bf16 g_Hhi[N_GRAPHS * HIDDEN_SIZE];
__device__ bf16 g_Hlo[N_GRAPHS * HIDDEN_SIZE];

// ---------------- helpers ----------------
__device__ __forceinline__ uint32_t smem_u32(const void* p) {
    uint32_t a;
    asm("{ .reg .u64 t; cvta.to.shared.u64 t, %1; cvt.u32.u64 %0, t; }" : "=r"(a) : "l"(p));
    return a;
}
__device__ __forceinline__ void cp16(uint32_t dst, const void* src) {
    asm volatile("cp.async.cg.shared.global [%0], [%1], 16;" :: "r"(dst), "l"(src));
}
__device__ __forceinline__ void cp_commit() {
    asm volatile("cp.async.commit_group;" ::: "memory");
}
template <int N>
__device__ __forceinline__ void cp_wait() {
    asm volatile("cp.async.wait_group %0;" :: "n"(N) : "memory");
}
__device__ __forceinline__ void split_bf(float v, bf16& hi, bf16& lo) {
    hi = __float2bfloat16(v);
    lo = __float2bfloat16(v - __bfloat162float(hi));
}
__device__ __forceinline__ float selu_f(float v) {
    const float alpha = 1.6732632423543772f;
    const float scale = 1.0507009873554805f;
    return v > 0.0f ? scale * v : scale * alpha * (expf(v) - 1.0f);
}

// ---------------- kernel 1: fused per-graph mean + concat (-> bf16 splits) ----
__global__ __launch_bounds__(128) void mean_concat_kernel(
    const float* __restrict__ x, const int* __restrict__ batch,
    const float* __restrict__ u)
{
    const int g = blockIdx.x;
    const int tid = threadIdx.x;

    int lo = 0, hi = N_NODES;
    while (lo < hi) { int mid = (lo + hi) >> 1; if (__ldg(&batch[mid]) < g) lo = mid + 1; else hi = mid; }
    const int start = lo;
    hi = N_NODES;
    while (lo < hi) { int mid = (lo + hi) >> 1; if (__ldg(&batch[mid]) < g + 1) lo = mid + 1; else hi = mid; }
    const int end = lo;

    float4 acc = make_float4(0.f, 0.f, 0.f, 0.f);
    const float* xp = x + (size_t)start * NODE_SIZE + tid * 4;
#pragma unroll 4
    for (int r = start; r < end; ++r) {
        float4 v = *(const float4*)xp;
        acc.x += v.x; acc.y += v.y; acc.z += v.z; acc.w += v.w;
        xp += NODE_SIZE;
    }
    const int cnt = end - start;
    const float inv = (cnt > 0) ? 1.0f / (float)cnt : 0.0f;
    acc.x *= inv; acc.y *= inv; acc.z *= inv; acc.w *= inv;

    {
        size_t base = (size_t)g * INPUT_SIZE + GLOBAL_SIZE + tid * 4;
        bf16 h, l;
        split_bf(acc.x, h, l); g_Ahi[base]     = h; g_Alo[base]     = l;
        split_bf(acc.y, h, l); g_Ahi[base + 1] = h; g_Alo[base + 1] = l;
        split_bf(acc.z, h, l); g_Ahi[base + 2] = h; g_Alo[base + 2] = l;
        split_bf(acc.w, h, l); g_Ahi[base + 3] = h; g_Alo[base + 3] = l;
    }
    if (tid < GLOBAL_SIZE / 4) {
        float4 v = *(const float4*)&u[(size_t)g * GLOBAL_SIZE + tid * 4];
        size_t base = (size_t)g * INPUT_SIZE + tid * 4;
        bf16 h, l;
        split_bf(v.x, h, l); g_Ahi[base]     = h; g_Alo[base]     = l;
        split_bf(v.y, h, l); g_Ahi[base + 1] = h; g_Alo[base + 1] = l;
        split_bf(v.z, h, l); g_Ahi[base + 2] = h; g_Alo[base + 2] = l;
        split_bf(v.w, h, l); g_Ahi[base + 3] = h; g_Alo[base + 3] = l;
    }
}

// ---------------- prep: transpose + split weights ----------------
__global__ void prep_w1t_kernel(const float* __restrict__ W1) {
    int idx = blockIdx.x * blockDim.x + threadIdx.x;
    if (idx >= HIDDEN_SIZE * INPUT_SIZE) return;
    int n = idx / INPUT_SIZE, k = idx % INPUT_SIZE;
    float v = __ldg(&W1[(size_t)k * HIDDEN_SIZE + n]);
    bf16 hi, lo; split_bf(v, hi, lo);
    g_W1Thi[idx] = hi; g_W1Tlo[idx] = lo;
}
__global__ void prep_w2t_kernel(const float* __restrict__ W2) {
    int idx = blockIdx.x * blockDim.x + threadIdx.x;
    if (idx >= GLOBAL_SIZE * HIDDEN_SIZE) return;
    int n = idx / HIDDEN_SIZE, k = idx % HIDDEN_SIZE;
    float v = __ldg(&W2[(size_t)k * GLOBAL_SIZE + n]);
    bf16 hi, lo; split_bf(v, hi, lo);
    g_W2Thi[idx] = hi; g_W2Tlo[idx] = lo;
}

// ---------------- cp.async double-buffered wmma bf16-split GEMM ---------------
// C = A @ B^T, fp32 accum; 3 passes AhBh + AhBl + AlBh. BN=128, BK=32, PAD=40.
// 256 threads = 8 warps (2M x 4N), warp tile (BM/2) x 32.
// Epilogue stages C in smem, applies EPI (bias [+ SELU + split]).
template <int BM, bool DO_SELU>
__device__ __forceinline__ void gemm_pipe_body(
    const bf16* __restrict__ Ah, const bf16* __restrict__ Al,
    const bf16* __restrict__ Bh, const bf16* __restrict__ Bl,
    const float* __restrict__ bias,
    bf16* __restrict__ Chi, bf16* __restrict__ Clo, float* __restrict__ Cf,
    int K_TOTAL, int N_TOTAL)
{
    constexpr int BN = 128, BK = 32, PAD = 40;   // 80B rows (16B-aligned)
    constexpr int WM = BM / 2;
    constexpr int MF = WM / 16;
    constexpr int NF = 2;
    constexpr int ATILE = BM * PAD;              // bf16 elems
    constexpr int BTILE = BN * PAD;
    constexpr int STAGE = 2 * ATILE + 2 * BTILE; // Ah,Al,Bh,Bl
    constexpr int CLD = 132;                     // staging ld (fp32)

    extern __shared__ __align__(16) char sm_raw[];
    bf16* sm = (bf16*)sm_raw;
    const uint32_t sm_base = smem_u32(sm);

    const int tid = threadIdx.x;
    const int wid = tid >> 5;
    const int warp_m = wid >> 2;
    const int warp_n = wid & 3;
    const int m0 = blockIdx.y * BM;
    const int n0 = blockIdx.x * BN;

    wmma::fragment<wmma::accumulator, 16, 16, 16, float> acc[MF][NF];
#pragma unroll
    for (int mi = 0; mi < MF; ++mi)
#pragma unroll
        for (int ni = 0; ni < NF; ++ni) wmma::fill_fragment(acc[mi][ni], 0.0f);

    // issue cp.async loads for K-chunk t into stage s
    auto load_stage = [&](int s, int t) {
        const int k0 = t * BK;
        const uint32_t sb = sm_base + (uint32_t)s * STAGE * 2;
#pragma unroll
        for (int q = 0; q < BM * 4 / 256; ++q) {
            int idx = tid + q * 256;
            int r = idx >> 2, c8 = (idx & 3) * 8;
            uint32_t d = sb + (uint32_t)(r * PAD + c8) * 2;
            cp16(d,                          &Ah[(size_t)(m0 + r) * K_TOTAL + k0 + c8]);
            cp16(d + (uint32_t)ATILE * 2,    &Al[(size_t)(m0 + r) * K_TOTAL + k0 + c8]);
        }
#pragma unroll
        for (int q = 0; q < BN * 4 / 256; ++q) {
            int idx = tid + q * 256;
            int r = idx >> 2, c8 = (idx & 3) * 8;
            uint32_t d = sb + (uint32_t)(2 * ATILE + r * PAD + c8) * 2;
            cp16(d,                          &Bh[(size_t)(n0 + r) * K_TOTAL + k0 + c8]);
            cp16(d + (uint32_t)BTILE * 2,    &Bl[(size_t)(n0 + r) * K_TOTAL + k0 + c8]);
        }
        cp_commit();
    };

    auto compute_stage = [&](int s) {
        bf16* sAh = sm + (size_t)s * STAGE;
        bf16* sAl = sAh + ATILE;
        bf16* sBh = sAl + ATILE;
        bf16* sBl = sBh + BTILE;
#pragma unroll
        for (int ks = 0; ks < BK / 16; ++ks) {
            wmma::fragment<wmma::matrix_b, 16, 16, 16, bf16, wmma::col_major> fbh[NF], fbl[NF];
#pragma unroll
            for (int ni = 0; ni < NF; ++ni) {
                wmma::load_matrix_sync(fbh[ni], &sBh[(warp_n * 32 + ni * 16) * PAD + ks * 16], PAD);
                wmma::load_matrix_sync(fbl[ni], &sBl[(warp_n * 32 + ni * 16) * PAD + ks * 16], PAD);
            }
#pragma unroll
            for (int mi = 0; mi < MF; ++mi) {
                wmma::fragment<wmma::matrix_a, 16, 16, 16, bf16, wmma::row_major> fah, fal;
                wmma::load_matrix_sync(fah, &sAh[(warp_m * WM + mi * 16) * PAD + ks * 16], PAD);
                wmma::load_matrix_sync(fal, &sAl[(warp_m * WM + mi * 16) * PAD + ks * 16], PAD);
#pragma unroll
                for (int ni = 0; ni < NF; ++ni) {
                    wmma::mma_sync(acc[mi][ni], fah, fbh[ni], acc[mi][ni]);
                    wmma::mma_sync(acc[mi][ni], fah, fbl[ni], acc[mi][ni]);
                    wmma::mma_sync(acc[mi][ni], fal, fbh[ni], acc[mi][ni]);
                }
            }
        }
    };

    const int nk = K_TOTAL / BK;
    load_stage(0, 0);
    for (int t = 0; t < nk; ++t) {
        if (t + 1 < nk) {
            load_stage((t + 1) & 1, t + 1);
            cp_wait<1>();
        } else {
            cp_wait<0>();
        }
        __syncthreads();
        compute_stage(t & 1);
        __syncthreads();
    }

    // ---- fused epilogue via smem staging ----
    float* sC = (float*)sm;
#pragma unroll
    for (int mi = 0; mi < MF; ++mi)
#pragma unroll
        for (int ni = 0; ni < NF; ++ni)
            wmma::store_matrix_sync(
                &sC[(warp_m * WM + mi * 16) * CLD + warp_n * 32 + ni * 16],
                acc[mi][ni], CLD, wmma::mem_row_major);
    __syncthreads();

    for (int idx = tid; idx < BM * (BN / 4); idx += 256) {
        int r = idx / (BN / 4);
        int c = (idx % (BN / 4)) * 4;
        float4 bv = *(const float4*)&bias[n0 + c];
        float v0 = sC[r * CLD + c]     + bv.x;
        float v1 = sC[r * CLD + c + 1] + bv.y;
        float v2 = sC[r * CLD + c + 2] + bv.z;
        float v3 = sC[r * CLD + c + 3] + bv.w;
        if (DO_SELU) {
            v0 = selu_f(v0); v1 = selu_f(v1); v2 = selu_f(v2); v3 = selu_f(v3);
            bf16 h0, l0, h1, l1, h2, l2, h3, l3;
            split_bf(v0, h0, l0); split_bf(v1, h1, l1);
            split_bf(v2, h2, l2); split_bf(v3, h3, l3);
            size_t o = (size_t)(m0 + r) * N_TOTAL + n0 + c;
            *(__nv_bfloat162*)&Chi[o]     = __nv_bfloat162(h0, h1);
            *(__nv_bfloat162*)&Chi[o + 2] = __nv_bfloat162(h2, h3);
            *(__nv_bfloat162*)&Clo[o]     = __nv_bfloat162(l0, l1);
            *(__nv_bfloat162*)&Clo[o + 2] = __nv_bfloat162(l2, l3);
        } else {
            float4 o4; o4.x = v0; o4.y = v1; o4.z = v2; o4.w = v3;
            *(float4*)&Cf[(size_t)(m0 + r) * N_TOTAL + n0 + c] = o4;
        }
    }
}

// Wrappers: device-global scratch referenced FROM DEVICE CODE only.
__global__ __launch_bounds__(256) void gemm1_kernel(const float* __restrict__ b1) {
    gemm_pipe_body<128, true>(g_Ahi, g_Alo, g_W1Thi, g_W1Tlo, b1,
                              g_Hhi, g_Hlo, nullptr, INPUT_SIZE, HIDDEN_SIZE);
}
__global__ __launch_bounds__(256) void gemm2_kernel(float* __restrict__ out,
                                                    const float* __restrict__ b2) {
    gemm_pipe_body<64, false>(g_Hhi, g_Hlo, g_W2Thi, g_W2Tlo, b2,
                              nullptr, nullptr, out, HIDDEN_SIZE, GLOBAL_SIZE);
}

// ---------------- launch ----------------
extern "C" void kernel_launch(void* const* d_in, const int* in_sizes, int n_in,
                              void* d_out, int out_size)
{
    const float* x     = nullptr;   // 256,000,000
    const float* u     = nullptr;   //   1,048,576
    const int*   batch = nullptr;   //     500,000 (int32 on device)
    const float* W1    = nullptr;   //     786,432
    const float* b1    = nullptr;   //       1,024
    const float* W2    = nullptr;   //     262,144
    const float* b2    = nullptr;   //         256

    for (int i = 0; i < n_in; ++i) {
        switch (in_sizes[i]) {
            case 256000000: x     = (const float*)d_in[i]; break;
            case 1048576:   u     = (const float*)d_in[i]; break;
            case 500000:    batch = (const int*)d_in[i];   break;
            case 786432:    W1    = (const float*)d_in[i]; break;
            case 1024:      b1    = (const float*)d_in[i]; break;
            case 262144:    W2    = (const float*)d_in[i]; break;
            case 256:       b2    = (const float*)d_in[i]; break;
            default: break; // edge_index (2000), edge_attr (16000): unused
        }
    }
    float* out = (float*)d_out;
    if (!x || !u || !batch || !W1 || !b1 || !W2 || !b2) return;

    constexpr int PAD = 40, CLD = 132;
    // gemm1: 2 stages x (2*128*PAD + 2*128*PAD) bf16; staging 128*CLD fp32
    const int stage1 = (2 * 128 * PAD + 2 * 128 * PAD) * 2;
    const int smem1  = (2 * stage1 > 128 * CLD * 4) ? 2 * stage1 : 128 * CLD * 4;
    // gemm2: 2 stages x (2*64*PAD + 2*128*PAD) bf16; staging 64*CLD fp32
    const int stage2 = (2 * 64 * PAD + 2 * 128 * PAD) * 2;
    const int smem2  = (2 * stage2 > 64 * CLD * 4) ? 2 * stage2 : 64 * CLD * 4;
    cudaFuncSetAttribute(gemm1_kernel,
                         cudaFuncAttributeMaxDynamicSharedMemorySize, smem1);
    cudaFuncSetAttribute(gemm2_kernel,
                         cudaFuncAttributeMaxDynamicSharedMemorySize, smem2);

    // 1. A = [u | segment_mean(x, batch)]  (bf16 hi/lo)
    mean_concat_kernel<<<N_GRAPHS, 128>>>(x, batch, u);

    // 2. weight transpose + split
    prep_w1t_kernel<<<(HIDDEN_SIZE * INPUT_SIZE + 255) / 256, 256>>>(W1);
    prep_w2t_kernel<<<(GLOBAL_SIZE * HIDDEN_SIZE + 255) / 256, 256>>>(W2);

    // 3. H = selu(A @ W1 + b1) -> bf16 hi/lo   [4096 x 1024]
    {
        dim3 grid(HIDDEN_SIZE / 128, N_GRAPHS / 128);
        gemm1_kernel<<<grid, 256, smem1>>>(b1);
    }
    // 4. out = H @ W2 + b2  (fp32)             [4096 x 256]
    {
        dim3 grid(GLOBAL_SIZE / 128, N_GRAPHS / 64);
        gemm2_kernel<<<grid, 256, smem2>>>(out, b2);
    }
}

// round 10
// speedup vs baseline: 1.6599x; 1.0454x over previous
#include <cuda_runtime.h>
#include <cuda_bf16.h>
#include <mma.h>
#include <cstdint>

using namespace nvcuda;

#define N_NODES     500000
#define NODE_SIZE   512
#define GLOBAL_SIZE 256
#define HIDDEN_SIZE 1024
#define N_GRAPHS    4096
#define INPUT_SIZE  768

typedef __nv_bfloat16 bf16;

// ---------------- scratch (device globals; no allocation) ----------------
__device__ bf16 g_Ahi[N_GRAPHS * INPUT_SIZE];
__device__ bf16 g_Alo[N_GRAPHS * INPUT_SIZE];
__device__ bf16 g_W1Thi[HIDDEN_SIZE * INPUT_SIZE];   // [N=1024][K=768]
__device__ bf16 g_W1Tlo[HIDDEN_SIZE * INPUT_SIZE];
__device__ bf16 g_W2Thi[GLOBAL_SIZE * HIDDEN_SIZE];  // [N=256][K=1024]
__device__ bf16 g_W2Tlo[GLOBAL_SIZE * HIDDEN_SIZE];
__device__ bf16 g_Hhi[N_GRAPHS * HIDDEN_SIZE];
__device__ bf16 g_Hlo[N_GRAPHS * HIDDEN_SIZE];

// ---------------- helpers ----------------
__device__ __forceinline__ uint32_t smem_u32(const void* p) {
    uint32_t a;
    asm("{ .reg .u64 t; cvta.to.shared.u64 t, %1; cvt.u32.u64 %0, t; }" : "=r"(a) : "l"(p));
    return a;
}
__device__ __forceinline__ void cp16(uint32_t dst, const void* src) {
    asm volatile("cp.async.cg.shared.global [%0], [%1], 16;" :: "r"(dst), "l"(src));
}
__device__ __forceinline__ void cp_commit() {
    asm volatile("cp.async.commit_group;" ::: "memory");
}
template <int N>
__device__ __forceinline__ void cp_wait() {
    asm volatile("cp.async.wait_group %0;" :: "n"(N) : "memory");
}
__device__ __forceinline__ void split_bf(float v, bf16& hi, bf16& lo) {
    hi = __float2bfloat16(v);
    lo = __float2bfloat16(v - __bfloat162float(hi));
}
__device__ __forceinline__ float selu_f(float v) {
    const float alpha = 1.6732632423543772f;
    const float scale = 1.0507009873554805f;
    return v > 0.0f ? scale * v : scale * alpha * (expf(v) - 1.0f);
}

// ---------------- kernel 1: fused per-graph mean + concat (-> bf16 splits) ----
__global__ __launch_bounds__(128) void mean_concat_kernel(
    const float* __restrict__ x, const int* __restrict__ batch,
    const float* __restrict__ u)
{
    const int g = blockIdx.x;
    const int tid = threadIdx.x;

    int lo = 0, hi = N_NODES;
    while (lo < hi) { int mid = (lo + hi) >> 1; if (__ldg(&batch[mid]) < g) lo = mid + 1; else hi = mid; }
    const int start = lo;
    hi = N_NODES;
    while (lo < hi) { int mid = (lo + hi) >> 1; if (__ldg(&batch[mid]) < g + 1) lo = mid + 1; else hi = mid; }
    const int end = lo;

    float4 acc = make_float4(0.f, 0.f, 0.f, 0.f);
    const float* xp = x + (size_t)start * NODE_SIZE + tid * 4;
#pragma unroll 4
    for (int r = start; r < end; ++r) {
        float4 v = *(const float4*)xp;
        acc.x += v.x; acc.y += v.y; acc.z += v.z; acc.w += v.w;
        xp += NODE_SIZE;
    }
    const int cnt = end - start;
    const float inv = (cnt > 0) ? 1.0f / (float)cnt : 0.0f;
    acc.x *= inv; acc.y *= inv; acc.z *= inv; acc.w *= inv;

    {
        size_t base = (size_t)g * INPUT_SIZE + GLOBAL_SIZE + tid * 4;
        bf16 h, l;
        split_bf(acc.x, h, l); g_Ahi[base]     = h; g_Alo[base]     = l;
        split_bf(acc.y, h, l); g_Ahi[base + 1] = h; g_Alo[base + 1] = l;
        split_bf(acc.z, h, l); g_Ahi[base + 2] = h; g_Alo[base + 2] = l;
        split_bf(acc.w, h, l); g_Ahi[base + 3] = h; g_Alo[base + 3] = l;
    }
    if (tid < GLOBAL_SIZE / 4) {
        float4 v = *(const float4*)&u[(size_t)g * GLOBAL_SIZE + tid * 4];
        size_t base = (size_t)g * INPUT_SIZE + tid * 4;
        bf16 h, l;
        split_bf(v.x, h, l); g_Ahi[base]     = h; g_Alo[base]     = l;
        split_bf(v.y, h, l); g_Ahi[base + 1] = h; g_Alo[base + 1] = l;
        split_bf(v.z, h, l); g_Ahi[base + 2] = h; g_Alo[base + 2] = l;
        split_bf(v.w, h, l); g_Ahi[base + 3] = h; g_Alo[base + 3] = l;
    }
}

// ---------------- prep: tiled transpose + split weights ----------------
// W: [K][N] fp32 row-major -> WT hi/lo: [N][K] bf16.  32x32 tiles via smem.
template <int KDIM, int NDIM>
__global__ __launch_bounds__(256) void prep_wt_kernel(
    const float* __restrict__ W, bf16* __restrict__ WThi, bf16* __restrict__ WTlo)
{
    __shared__ float tile[32][33];
    const int tx = threadIdx.x & 31;      // 0..31
    const int ty = threadIdx.x >> 5;      // 0..7
    const int k0 = blockIdx.y * 32;
    const int n0 = blockIdx.x * 32;

#pragma unroll
    for (int q = 0; q < 4; ++q) {
        int k = k0 + ty + q * 8;
        tile[ty + q * 8][tx] = __ldg(&W[(size_t)k * NDIM + n0 + tx]);
    }
    __syncthreads();
#pragma unroll
    for (int q = 0; q < 4; ++q) {
        int n = n0 + ty + q * 8;
        float v = tile[tx][ty + q * 8];
        bf16 hi, lo; split_bf(v, hi, lo);
        WThi[(size_t)n * KDIM + k0 + tx] = hi;
        WTlo[(size_t)n * KDIM + k0 + tx] = lo;
    }
}
__global__ __launch_bounds__(256) void prep_w1_kernel(const float* __restrict__ W1) {
    // wrapper so device symbols are referenced from device code
    __shared__ float tile[32][33];
    const int tx = threadIdx.x & 31;
    const int ty = threadIdx.x >> 5;
    const int k0 = blockIdx.y * 32;
    const int n0 = blockIdx.x * 32;
#pragma unroll
    for (int q = 0; q < 4; ++q)
        tile[ty + q * 8][tx] = __ldg(&W1[(size_t)(k0 + ty + q * 8) * HIDDEN_SIZE + n0 + tx]);
    __syncthreads();
#pragma unroll
    for (int q = 0; q < 4; ++q) {
        int n = n0 + ty + q * 8;
        float v = tile[tx][ty + q * 8];
        bf16 hi, lo; split_bf(v, hi, lo);
        g_W1Thi[(size_t)n * INPUT_SIZE + k0 + tx] = hi;
        g_W1Tlo[(size_t)n * INPUT_SIZE + k0 + tx] = lo;
    }
}
__global__ __launch_bounds__(256) void prep_w2_kernel(const float* __restrict__ W2) {
    __shared__ float tile[32][33];
    const int tx = threadIdx.x & 31;
    const int ty = threadIdx.x >> 5;
    const int k0 = blockIdx.y * 32;
    const int n0 = blockIdx.x * 32;
#pragma unroll
    for (int q = 0; q < 4; ++q)
        tile[ty + q * 8][tx] = __ldg(&W2[(size_t)(k0 + ty + q * 8) * GLOBAL_SIZE + n0 + tx]);
    __syncthreads();
#pragma unroll
    for (int q = 0; q < 4; ++q) {
        int n = n0 + ty + q * 8;
        float v = tile[tx][ty + q * 8];
        bf16 hi, lo; split_bf(v, hi, lo);
        g_W2Thi[(size_t)n * HIDDEN_SIZE + k0 + tx] = hi;
        g_W2Tlo[(size_t)n * HIDDEN_SIZE + k0 + tx] = lo;
    }
}

// ---------------- cp.async double-buffered wmma bf16-split GEMM ---------------
// C = A @ B^T, fp32 accum; 3 passes AhBh + AhBl + AlBh. BN=128, BK=32, PAD=40.
// 256 threads = 8 warps (2M x 4N), warp tile (BM/2) x 32.
template <int BM, bool DO_SELU>
__device__ __forceinline__ void gemm_pipe_body(
    const bf16* __restrict__ Ah, const bf16* __restrict__ Al,
    const bf16* __restrict__ Bh, const bf16* __restrict__ Bl,
    const float* __restrict__ bias,
    bf16* __restrict__ Chi, bf16* __restrict__ Clo, float* __restrict__ Cf,
    int K_TOTAL, int N_TOTAL)
{
    constexpr int BN = 128, BK = 32, PAD = 40;   // 80B rows (16B-aligned)
    constexpr int WM = BM / 2;
    constexpr int MF = WM / 16;
    constexpr int NF = 2;
    constexpr int ATILE = BM * PAD;              // bf16 elems
    constexpr int BTILE = BN * PAD;
    constexpr int STAGE = 2 * ATILE + 2 * BTILE;
    constexpr int CLD = 132;                     // staging ld (fp32)

    extern __shared__ __align__(16) char sm_raw[];
    bf16* sm = (bf16*)sm_raw;
    const uint32_t sm_base = smem_u32(sm);

    const int tid = threadIdx.x;
    const int wid = tid >> 5;
    const int warp_m = wid >> 2;
    const int warp_n = wid & 3;
    const int m0 = blockIdx.y * BM;
    const int n0 = blockIdx.x * BN;

    wmma::fragment<wmma::accumulator, 16, 16, 16, float> acc[MF][NF];
#pragma unroll
    for (int mi = 0; mi < MF; ++mi)
#pragma unroll
        for (int ni = 0; ni < NF; ++ni) wmma::fill_fragment(acc[mi][ni], 0.0f);

    auto load_stage = [&](int s, int t) {
        const int k0 = t * BK;
        const uint32_t sb = sm_base + (uint32_t)s * STAGE * 2;
#pragma unroll
        for (int q = 0; q < BM * 4 / 256; ++q) {
            int idx = tid + q * 256;
            int r = idx >> 2, c8 = (idx & 3) * 8;
            uint32_t d = sb + (uint32_t)(r * PAD + c8) * 2;
            cp16(d,                       &Ah[(size_t)(m0 + r) * K_TOTAL + k0 + c8]);
            cp16(d + (uint32_t)ATILE * 2, &Al[(size_t)(m0 + r) * K_TOTAL + k0 + c8]);
        }
#pragma unroll
        for (int q = 0; q < BN * 4 / 256; ++q) {
            int idx = tid + q * 256;
            int r = idx >> 2, c8 = (idx & 3) * 8;
            uint32_t d = sb + (uint32_t)(2 * ATILE + r * PAD + c8) * 2;
            cp16(d,                       &Bh[(size_t)(n0 + r) * K_TOTAL + k0 + c8]);
            cp16(d + (uint32_t)BTILE * 2, &Bl[(size_t)(n0 + r) * K_TOTAL + k0 + c8]);
        }
        cp_commit();
    };

    auto compute_stage = [&](int s) {
        bf16* sAh = sm + (size_t)s * STAGE;
        bf16* sAl = sAh + ATILE;
        bf16* sBh = sAl + ATILE;
        bf16* sBl = sBh + BTILE;
#pragma unroll
        for (int ks = 0; ks < BK / 16; ++ks) {
            wmma::fragment<wmma::matrix_b, 16, 16, 16, bf16, wmma::col_major> fbh[NF], fbl[NF];
#pragma unroll
            for (int ni = 0; ni < NF; ++ni) {
                wmma::load_matrix_sync(fbh[ni], &sBh[(warp_n * 32 + ni * 16) * PAD + ks * 16], PAD);
                wmma::load_matrix_sync(fbl[ni], &sBl[(warp_n * 32 + ni * 16) * PAD + ks * 16], PAD);
            }
#pragma unroll
            for (int mi = 0; mi < MF; ++mi) {
                wmma::fragment<wmma::matrix_a, 16, 16, 16, bf16, wmma::row_major> fah, fal;
                wmma::load_matrix_sync(fah, &sAh[(warp_m * WM + mi * 16) * PAD + ks * 16], PAD);
                wmma::load_matrix_sync(fal, &sAl[(warp_m * WM + mi * 16) * PAD + ks * 16], PAD);
#pragma unroll
                for (int ni = 0; ni < NF; ++ni) {
                    wmma::mma_sync(acc[mi][ni], fah, fbh[ni], acc[mi][ni]);
                    wmma::mma_sync(acc[mi][ni], fah, fbl[ni], acc[mi][ni]);
                    wmma::mma_sync(acc[mi][ni], fal, fbh[ni], acc[mi][ni]);
                }
            }
        }
    };

    const int nk = K_TOTAL / BK;
    load_stage(0, 0);
    for (int t = 0; t < nk; ++t) {
        if (t + 1 < nk) {
            load_stage((t + 1) & 1, t + 1);
            cp_wait<1>();
        } else {
            cp_wait<0>();
        }
        __syncthreads();
        compute_stage(t & 1);
        __syncthreads();
    }

    // ---- fused epilogue via smem staging ----
    float* sC = (float*)sm;
#pragma unroll
    for (int mi = 0; mi < MF; ++mi)
#pragma unroll
        for (int ni = 0; ni < NF; ++ni)
            wmma::store_matrix_sync(
                &sC[(warp_m * WM + mi * 16) * CLD + warp_n * 32 + ni * 16],
                acc[mi][ni], CLD, wmma::mem_row_major);
    __syncthreads();

    for (int idx = tid; idx < BM * (BN / 4); idx += 256) {
        int r = idx / (BN / 4);
        int c = (idx % (BN / 4)) * 4;
        float4 bv = *(const float4*)&bias[n0 + c];
        float v0 = sC[r * CLD + c]     + bv.x;
        float v1 = sC[r * CLD + c + 1] + bv.y;
        float v2 = sC[r * CLD + c + 2] + bv.z;
        float v3 = sC[r * CLD + c + 3] + bv.w;
        if (DO_SELU) {
            v0 = selu_f(v0); v1 = selu_f(v1); v2 = selu_f(v2); v3 = selu_f(v3);
            bf16 h0, l0, h1, l1, h2, l2, h3, l3;
            split_bf(v0, h0, l0); split_bf(v1, h1, l1);
            split_bf(v2, h2, l2); split_bf(v3, h3, l3);
            size_t o = (size_t)(m0 + r) * N_TOTAL + n0 + c;
            *(__nv_bfloat162*)&Chi[o]     = __nv_bfloat162(h0, h1);
            *(__nv_bfloat162*)&Chi[o + 2] = __nv_bfloat162(h2, h3);
            *(__nv_bfloat162*)&Clo[o]     = __nv_bfloat162(l0, l1);
            *(__nv_bfloat162*)&Clo[o + 2] = __nv_bfloat162(l2, l3);
        } else {
            float4 o4; o4.x = v0; o4.y = v1; o4.z = v2; o4.w = v3;
            *(float4*)&Cf[(size_t)(m0 + r) * N_TOTAL + n0 + c] = o4;
        }
    }
}

// Wrappers: device-global scratch referenced FROM DEVICE CODE only.
// minBlocksPerMultiprocessor=2 caps regs at 128 -> 2 CTAs/SM (regfile was the
// occupancy limiter at 134 regs).
__global__ __launch_bounds__(256, 2) void gemm1_kernel(const float* __restrict__ b1) {
    gemm_pipe_body<128, true>(g_Ahi, g_Alo, g_W1Thi, g_W1Tlo, b1,
                              g_Hhi, g_Hlo, nullptr, INPUT_SIZE, HIDDEN_SIZE);
}
__global__ __launch_bounds__(256, 2) void gemm2_kernel(float* __restrict__ out,
                                                       const float* __restrict__ b2) {
    gemm_pipe_body<64, false>(g_Hhi, g_Hlo, g_W2Thi, g_W2Tlo, b2,
                              nullptr, nullptr, out, HIDDEN_SIZE, GLOBAL_SIZE);
}

// ---------------- launch ----------------
extern "C" void kernel_launch(void* const* d_in, const int* in_sizes, int n_in,
                              void* d_out, int out_size)
{
    const float* x     = nullptr;   // 256,000,000
    const float* u     = nullptr;   //   1,048,576
    const int*   batch = nullptr;   //     500,000 (int32 on device)
    const float* W1    = nullptr;   //     786,432
    const float* b1    = nullptr;   //       1,024
    const float* W2    = nullptr;   //     262,144
    const float* b2    = nullptr;   //         256

    for (int i = 0; i < n_in; ++i) {
        switch (in_sizes[i]) {
            case 256000000: x     = (const float*)d_in[i]; break;
            case 1048576:   u     = (const float*)d_in[i]; break;
            case 500000:    batch = (const int*)d_in[i];   break;
            case 786432:    W1    = (const float*)d_in[i]; break;
            case 1024:      b1    = (const float*)d_in[i]; break;
            case 262144:    W2    = (const float*)d_in[i]; break;
            case 256:       b2    = (const float*)d_in[i]; break;
            default: break; // edge_index (2000), edge_attr (16000): unused
        }
    }
    float* out = (float*)d_out;
    if (!x || !u || !batch || !W1 || !b1 || !W2 || !b2) return;

    constexpr int PAD = 40, CLD = 132;
    const int stage1 = (2 * 128 * PAD + 2 * 128 * PAD) * 2;
    const int smem1  = (2 * stage1 > 128 * CLD * 4) ? 2 * stage1 : 128 * CLD * 4;
    const int stage2 = (2 * 64 * PAD + 2 * 128 * PAD) * 2;
    const int smem2  = (2 * stage2 > 64 * CLD * 4) ? 2 * stage2 : 64 * CLD * 4;
    cudaFuncSetAttribute(gemm1_kernel,
                         cudaFuncAttributeMaxDynamicSharedMemorySize, smem1);
    cudaFuncSetAttribute(gemm2_kernel,
                         cudaFuncAttributeMaxDynamicSharedMemorySize, smem2);

    // 1. A = [u | segment_mean(x, batch)]  (bf16 hi/lo)
    mean_concat_kernel<<<N_GRAPHS, 128>>>(x, batch, u);

    // 2. weight transpose + split (coalesced 32x32 tiles)
    {
        dim3 g1(HIDDEN_SIZE / 32, INPUT_SIZE / 32);
        prep_w1_kernel<<<g1, 256>>>(W1);
        dim3 g2(GLOBAL_SIZE / 32, HIDDEN_SIZE / 32);
        prep_w2_kernel<<<g2, 256>>>(W2);
    }

    // 3. H = selu(A @ W1 + b1) -> bf16 hi/lo   [4096 x 1024]
    {
        dim3 grid(HIDDEN_SIZE / 128, N_GRAPHS / 128);
        gemm1_kernel<<<grid, 256, smem1>>>(b1);
    }
    // 4. out = H @ W2 + b2  (fp32)             [4096 x 256]
    {
        dim3 grid(GLOBAL_SIZE / 128, N_GRAPHS / 64);
        gemm2_kernel<<<grid, 256, smem2>>>(out, b2);
    }
}